// round 13
// baseline (speedup 1.0000x reference)
#include <cuda_runtime.h>
#include <cuda_bf16.h>
#include <cstdint>
#include <math.h>

// Problem constants
#define T_DIM 256
#define B_DIM 256
#define I_DIM 9
#define H_DIM 1024
#define A_DIM 4
#define R_DIM 38

#define GRID_P 128          // persistent grid: 4 M-tiles x 32 N-tiles

// ---------------------------------------------------------------------------
// Device scratch
// g_A layout (per parity): 16 blocks x 256 rows x 128 cols bf16.
//   block 0..7  = hi part of col group [blk*128, blk*128+128)
//   block 8..15 = lo part of col group [(blk-8)*128, ...)
// Within a block, element (row, c) lives at:
//   blk*32768 + row*128 + (((c>>3) ^ (row&7))<<3) + (c&7)      (ldsm swizzle)
// => any 64-row m-slice of a block is one CONTIGUOUS 16KB chunk (bulk-copyable).
// ---------------------------------------------------------------------------
__device__ float          g_rbias[B_DIM * H_DIM];
__device__ __nv_bfloat16  g_Whi[H_DIM * H_DIM];          // [N][K] hi
__device__ __nv_bfloat16  g_Wlo[H_DIM * H_DIM];          // [N][K] lo
__device__ __nv_bfloat16  g_A[2][B_DIM * 2 * H_DIM];     // blocked+swizzled, ping-pong
__device__ unsigned       g_rdy[T_DIM * 4 * 8];          // dataflow counters

// ---------------------------------------------------------------------------
// Prep kernels
// ---------------------------------------------------------------------------
__global__ void rbias_kernel(const float* __restrict__ reward,
                             const float* __restrict__ r2h,
                             const float* __restrict__ bh) {
    int idx = blockIdx.x * blockDim.x + threadIdx.x;
    int h = idx & (H_DIM - 1);
    int b = idx >> 10;
    float s = bh[h];
    const float* rw = reward + b * R_DIM;
#pragma unroll
    for (int j = 0; j < R_DIM; ++j)
        s = fmaf(rw[j], r2h[j * H_DIM + h], s);
    g_rbias[idx] = s;
}

__global__ void wprep_kernel(const float* __restrict__ h2h) {
    __shared__ float tile[32][33];
    const int k0 = blockIdx.x * 32;
    const int n0 = blockIdx.y * 32;
    const int tid = threadIdx.x;
#pragma unroll
    for (int it = 0; it < 4; ++it) {
        int e = it * 256 + tid;
        int kk = e >> 5, nn = e & 31;
        tile[kk][nn] = h2h[(size_t)(k0 + kk) * H_DIM + n0 + nn];
    }
    __syncthreads();
#pragma unroll
    for (int it = 0; it < 2; ++it) {
        int e = it * 256 + tid;
        int nn = e >> 4, pp = e & 15;
        float w0 = tile[2 * pp][nn];
        float w1 = tile[2 * pp + 1][nn];
        __nv_bfloat16 h0 = __float2bfloat16(w0);
        __nv_bfloat16 h1 = __float2bfloat16(w1);
        __nv_bfloat16 l0 = __float2bfloat16(w0 - __bfloat162float(h0));
        __nv_bfloat16 l1 = __float2bfloat16(w1 - __bfloat162float(h1));
        size_t o = (size_t)(n0 + nn) * H_DIM + k0 + 2 * pp;
        *(__nv_bfloat162*)&g_Whi[o] = __nv_bfloat162(h0, h1);
        *(__nv_bfloat162*)&g_Wlo[o] = __nv_bfloat162(l0, l1);
    }
}

// element offset within one parity of g_A for (row, col) hi part
__device__ __forceinline__ int a_off_hi(int row, int col) {
    int blk = col >> 7, c = col & 127;
    return blk * 32768 + row * 128 + (((c >> 3) ^ (row & 7)) << 3) + (c & 7);
}

__global__ void conv_h0_kernel(const float* __restrict__ hidden0) {
    int idx = blockIdx.x * blockDim.x + threadIdx.x;
    int h = idx & (H_DIM - 1);
    int b = idx >> 10;
    float v = hidden0[idx];
    __nv_bfloat16 hi = __float2bfloat16(v);
    __nv_bfloat16 lo = __float2bfloat16(v - __bfloat162float(hi));
    int o = a_off_hi(b, h);
    g_A[0][o]          = hi;
    g_A[0][o + 262144] = lo;                     // +8 blocks * 32768
}

__global__ void zero_rdy_kernel() {
    g_rdy[blockIdx.x * 1024 + threadIdx.x] = 0u;
}

__device__ __forceinline__ float decode_k(const void* p) {
    int iv = *(const int*)p;
    float fv = __int_as_float(iv);
    float af = fabsf(fv);
    if (af >= 1e-30f && af <= 1e30f) return fv;
    return (float)iv;
}

// pre v3: block = fixed b, 64 timesteps; weights live in registers per thread.
__global__ void __launch_bounds__(256)
pre_kernel(const float* __restrict__ inputs,
           const float* __restrict__ actions,
           const float* __restrict__ i2h,
           const float* __restrict__ a2h,
           const void*  __restrict__ kact_ptr,
           float* __restrict__ out) {
    __shared__ float sinA[64 * I_DIM];
    __shared__ float sactA[64 * A_DIM];
    __shared__ float sk;
    const int b  = blockIdx.x & (B_DIM - 1);
    const int t0 = (blockIdx.x >> 8) << 6;
    const int tid = threadIdx.x;

    for (int e = tid; e < 64 * I_DIM; e += 256) {
        int j = e / I_DIM, i = e - j * I_DIM;
        sinA[e] = inputs[((size_t)(t0 + j) * B_DIM + b) * I_DIM + i];
    }
    for (int e = tid; e < 64 * A_DIM; e += 256) {
        int j = e >> 2, a = e & 3;
        sactA[e] = actions[((size_t)(t0 + j) * B_DIM + b) * A_DIM + a];
    }
    if (tid == 0) sk = decode_k(kact_ptr);
    __syncthreads();

    const int h = tid * 4;
    float4 rb = *(const float4*)&g_rbias[b * H_DIM + h];
    float4 wi[I_DIM], wa[A_DIM];
#pragma unroll
    for (int i = 0; i < I_DIM; ++i) wi[i] = *(const float4*)&i2h[i * H_DIM + h];
#pragma unroll
    for (int a = 0; a < A_DIM; ++a) wa[a] = *(const float4*)&a2h[a * H_DIM + h];
    const float k = sk;

    for (int j = 0; j < 64; ++j) {
        float4 s = rb;
#pragma unroll
        for (int i = 0; i < I_DIM; ++i) {
            float x = sinA[j * I_DIM + i];
            s.x = fmaf(x, wi[i].x, s.x); s.y = fmaf(x, wi[i].y, s.y);
            s.z = fmaf(x, wi[i].z, s.z); s.w = fmaf(x, wi[i].w, s.w);
        }
#pragma unroll
        for (int a = 0; a < A_DIM; ++a) {
            float x = k * sactA[j * A_DIM + a];
            s.x = fmaf(x, wa[a].x, s.x); s.y = fmaf(x, wa[a].y, s.y);
            s.z = fmaf(x, wa[a].z, s.z); s.w = fmaf(x, wa[a].w, s.w);
        }
        *(float4*)&out[((size_t)(t0 + j) * B_DIM + b) * H_DIM + h] = s;
    }
}

// ---------------------------------------------------------------------------
// Persistent recurrence kernel (bulk-copy A path)
// ---------------------------------------------------------------------------
__device__ __forceinline__ float tanh_fast(float x) {
    float e = __expf(2.0f * x);
    return 1.0f - __fdividef(2.0f, e + 1.0f);
}
__device__ __forceinline__ uint32_t smem_u32(const void* p) {
    uint32_t a;
    asm("{ .reg .u64 t; cvta.to.shared.u64 t, %1; cvt.u32.u64 %0, t; }" : "=r"(a) : "l"(p));
    return a;
}
__device__ __forceinline__ unsigned ld_acq(const unsigned* p) {
    unsigned v;
    asm volatile("ld.acquire.gpu.global.u32 %0, [%1];" : "=r"(v) : "l"(p) : "memory");
    return v;
}

#define MBARRIER_INIT(addr, cnt) \
    asm volatile("mbarrier.init.shared.b64 [%0], %1;" :: "r"((uint32_t)(addr)), "r"((uint32_t)(cnt)) : "memory")
#define MBARRIER_EXPECT_TX(addr, tx) \
    asm volatile("mbarrier.arrive.expect_tx.shared.b64 _, [%0], %1;" :: "r"((uint32_t)(addr)), "r"((uint32_t)(tx)) : "memory")
#define MBARRIER_WAIT_PARITY(addr, par) do { \
    uint32_t _mb = (uint32_t)(addr), _p = (uint32_t)(par), _d; \
    asm volatile("{\n\t.reg .pred p;\n\tmbarrier.try_wait.parity.acquire.cta.shared::cta.b64 p, [%1], %2;\n\tselp.b32 %0, 1, 0, p;\n\t}" \
        : "=r"(_d) : "r"(_mb), "r"(_p) : "memory"); \
    if (!_d) { \
        asm volatile("{\n\t.reg .pred P1;\n\tWL_%=:\n\tmbarrier.try_wait.parity.acquire.cta.shared::cta.b64 P1, [%0], %1, 0x989680;\n\t@P1 bra.uni WD_%=;\n\tbra.uni WL_%=;\n\tWD_%=:\n\t}" \
            :: "r"(_mb), "r"(_p) : "memory"); \
    } } while (0)
#define BULK_G2S(dst, src, sz, mbar) \
    asm volatile("cp.async.bulk.shared::cluster.global.mbarrier::complete_tx::bytes [%0], [%1], %2, [%3];" \
        :: "r"((uint32_t)(dst)), "l"(src), "r"((uint32_t)(sz)), "r"((uint32_t)(mbar)) : "memory")

__device__ __forceinline__ void mma16816(float* c, const uint32_t* a, const uint32_t* b) {
    asm volatile(
        "mma.sync.aligned.m16n8k16.row.col.f32.bf16.bf16.f32 "
        "{%0,%1,%2,%3}, {%4,%5,%6,%7}, {%8,%9}, {%0,%1,%2,%3};"
        : "+f"(c[0]), "+f"(c[1]), "+f"(c[2]), "+f"(c[3])
        : "r"(a[0]), "r"(a[1]), "r"(a[2]), "r"(a[3]), "r"(b[0]), "r"(b[1]));
}
__device__ __forceinline__ void ldsm4(uint32_t* r, uint32_t addr) {
    asm volatile("ldmatrix.sync.aligned.m8n8.x4.shared.b16 {%0,%1,%2,%3}, [%4];"
        : "=r"(r[0]), "=r"(r[1]), "=r"(r[2]), "=r"(r[3]) : "r"(addr));
}

// smem words: Whi[32][516] @0, Wlo @16512, A ring: 4 bufs of 64x64 words @33024
#define WS_STRIDE 516
#define WLO_OFF   16512
#define ABUF_OFF  33024
#define ABUF_SZ   4096
#define SMEM_P_WORDS (ABUF_OFF + 4 * ABUF_SZ)        // 49408
#define SMEM_P_BYTES (SMEM_P_WORDS * 4)              // 197632
#define NCHUNK 16

__global__ void __launch_bounds__(256, 1)
rnn_persistent(const float* __restrict__ hidden0,
               const float* __restrict__ rr,
               float* __restrict__ out) {
    extern __shared__ uint32_t smw[];
    __shared__ __align__(8) uint64_t mbar[4];

    const int tid  = threadIdx.x;
    const int wid  = tid >> 5;
    const int lane = tid & 31;
    const int gid  = lane >> 2;
    const int tig  = lane & 3;
    const int wm   = wid >> 1;           // 0..3 (16-row slabs)
    const int wn   = wid & 1;            // 0..1 (16-col slabs)
    const int n_grp = blockIdx.x & 31;
    const int m_grp = blockIdx.x >> 5;
    const int m0 = m_grp * 64;
    const int n0 = n_grp * 32;

    // ---- W slice (hi+lo) into smem once ----
    for (int e = tid; e < 32 * 128; e += 256) {
        int n = e >> 7, c = e & 127;
        uint4 vh = *(const uint4*)&g_Whi[(size_t)(n0 + n) * H_DIM + c * 8];
        uint4 vl = *(const uint4*)&g_Wlo[(size_t)(n0 + n) * H_DIM + c * 8];
        *(uint4*)&smw[n * WS_STRIDE + c * 4]           = vh;
        *(uint4*)&smw[WLO_OFF + n * WS_STRIDE + c * 4] = vl;
    }

    const uint32_t sbase = smem_u32(smw);
    const uint32_t mb0   = smem_u32(&mbar[0]);
    if (tid == 0) {
#pragma unroll
        for (int i = 0; i < 4; ++i) MBARRIER_INIT(mb0 + i * 8, 1);
        asm volatile("fence.proxy.async.shared::cta;" ::: "memory");
    }

    // ---- prev hidden tile + inertia in registers ----
    float hprev[2][4];
    float2 rv[2];
#pragma unroll
    for (int nt = 0; nt < 2; ++nt) {
        int c = n0 + wn * 16 + nt * 8 + tig * 2;
        rv[nt] = *(const float2*)&rr[c];
#pragma unroll
        for (int half = 0; half < 2; ++half) {
            int row = m0 + wm * 16 + gid + half * 8;
            float2 hp = *(const float2*)&hidden0[(size_t)row * H_DIM + c];
            hprev[nt][half * 2]     = hp.x;
            hprev[nt][half * 2 + 1] = hp.y;
        }
    }

    // A ldsm addressing: local row lr, swizzled seg = (2*k16 + lane>>4) ^ (lr&7)
    const int lr      = wm * 16 + (lane & 15);
    const int lr64    = lr * 64;
    const int lrx     = lr & 7;
    const int hi4     = lane >> 4;
    // B ldsm lane word-offsets (W layout unchanged)
    const int b_lane_row = wn * 16 + (lane & 7) + ((lane >> 4) << 3);
    const int b_lane_off = b_lane_row * WS_STRIDE + (((lane >> 3) & 1) << 2);

    // epilogue column -> block-local swizzled base (row added later)
    __syncthreads();

    for (int t = 0; t < T_DIM; ++t) {
        const __nv_bfloat16* __restrict__ A     = g_A[t & 1];
        __nv_bfloat16* __restrict__       Anext = g_A[(t + 1) & 1];
        float* __restrict__ outt = out + (size_t)t * (B_DIM * H_DIM);

        float acc[2][4];
#pragma unroll
        for (int nt = 0; nt < 2; ++nt)
#pragma unroll
            for (int q = 0; q < 4; ++q) acc[nt][q] = 0.f;

        // Prefetch pre tile into registers
        float2 pre_r[2][2];
#pragma unroll
        for (int nt = 0; nt < 2; ++nt) {
            const int c = n0 + wn * 16 + nt * 8 + tig * 2;
#pragma unroll
            for (int half = 0; half < 2; ++half) {
                const int row = m0 + wm * 16 + gid + half * 8;
                pre_r[nt][half] = *(const float2*)(outt + (size_t)row * H_DIM + c);
            }
        }

        // elected-thread issue: acquire-poll producers, then bulk-copy chunk
        auto issue = [&](int c) {
            if (tid != 0) return;
            if (t > 0 && c < 8) {
                const unsigned* p = &g_rdy[((t << 2) + m_grp) * 8 + c];
                while (ld_acq(p) < 4u) __nanosleep(40);
            }
            asm volatile("fence.proxy.async;" ::: "memory");
            const uint32_t mb = mb0 + (c & 3) * 8;
            MBARRIER_EXPECT_TX(mb, 16384);
            BULK_G2S(sbase + (uint32_t)(ABUF_OFF + (c & 3) * ABUF_SZ) * 4,
                     (const void*)(A + (size_t)c * 32768 + m0 * 128),
                     16384, mb);
        };

        auto mma_chunk = [&](int c) {
            const int abuf_w = ABUF_OFF + (c & 3) * ABUF_SZ;
            const int kw = (c & 7) << 6;           // chunk word offset in W rows
            const bool hi = (c < 8);
#pragma unroll
            for (int k16 = 0; k16 < 8; ++k16) {
                uint32_t af[4];
                const int seg = (2 * k16 + hi4) ^ lrx;
                ldsm4(af, sbase + (uint32_t)(abuf_w + lr64 + seg * 4) * 4);
                const int kb = kw + k16 * 8;
                uint32_t bh_[4];
                ldsm4(bh_, sbase + (uint32_t)(b_lane_off + kb) * 4);
                mma16816(acc[0], af, bh_);
                mma16816(acc[1], af, bh_ + 2);
                if (hi) {
                    uint32_t bl_[4];
                    ldsm4(bl_, sbase + (uint32_t)(WLO_OFF + b_lane_off + kb) * 4);
                    mma16816(acc[0], af, bl_);
                    mma16816(acc[1], af, bl_ + 2);
                }
            }
        };

        issue(0); issue(1); issue(2); issue(3);

        // pairs: wait mbarriers, MMA both, sync (buffer reuse), issue next two
        for (int p = 0; p < NCHUNK / 2; ++p) {
            const int c0 = 2 * p, c1 = 2 * p + 1;
            MBARRIER_WAIT_PARITY(mb0 + (c0 & 3) * 8, (c0 >> 2) & 1);
            mma_chunk(c0);
            MBARRIER_WAIT_PARITY(mb0 + (c1 & 3) * 8, (c1 >> 2) & 1);
            mma_chunk(c1);
            __syncthreads();
            if (c0 + 4 < NCHUNK) { issue(c0 + 4); issue(c1 + 4); }
        }

        // ---- epilogue: tanh + blend; publish Anext (blocked+swizzled); release ----
#pragma unroll
        for (int nt = 0; nt < 2; ++nt) {
            const int ccol = n0 + wn * 16 + nt * 8 + tig * 2;
            const int blkb = (ccol >> 7) * 32768;
            const int cin  = ccol & 127;
#pragma unroll
            for (int half = 0; half < 2; ++half) {
                const int row = m0 + wm * 16 + gid + half * 8;
                float tt, h0, h1;
                tt = tanh_fast(pre_r[nt][half].x + acc[nt][half * 2]);
                h0 = tt + rv[nt].x * (hprev[nt][half * 2] - tt);
                tt = tanh_fast(pre_r[nt][half].y + acc[nt][half * 2 + 1]);
                h1 = tt + rv[nt].y * (hprev[nt][half * 2 + 1] - tt);
                hprev[nt][half * 2]     = h0;
                hprev[nt][half * 2 + 1] = h1;

                if (t < T_DIM - 1) {
                    __nv_bfloat16 a0 = __float2bfloat16(h0);
                    __nv_bfloat16 a1 = __float2bfloat16(h1);
                    const int o = blkb + row * 128
                                + (((cin >> 3) ^ (row & 7)) << 3) + (cin & 7);
                    *(__nv_bfloat162*)&Anext[o] = __nv_bfloat162(a0, a1);
                    __nv_bfloat16 l0 = __float2bfloat16(h0 - __bfloat162float(a0));
                    __nv_bfloat16 l1 = __float2bfloat16(h1 - __bfloat162float(a1));
                    *(__nv_bfloat162*)&Anext[o + 262144] = __nv_bfloat162(l0, l1);
                }
            }
        }

        if (t < T_DIM - 1) {
            __threadfence();
            __syncthreads();
            if (tid == 0) {
                asm volatile("red.release.gpu.global.add.u32 [%0], 1;"
                    :: "l"(&g_rdy[(((t + 1) << 2) + m_grp) * 8 + (n_grp >> 2)])
                    : "memory");
            }
        }

        // deferred fp32 out store (off the inter-CTA critical path)
#pragma unroll
        for (int nt = 0; nt < 2; ++nt) {
            const int c = n0 + wn * 16 + nt * 8 + tig * 2;
#pragma unroll
            for (int half = 0; half < 2; ++half) {
                const int row = m0 + wm * 16 + gid + half * 8;
                *(float2*)(outt + (size_t)row * H_DIM + c) =
                    make_float2(hprev[nt][half * 2], hprev[nt][half * 2 + 1]);
            }
        }
    }
}

// ---------------------------------------------------------------------------
// Launch
// ---------------------------------------------------------------------------
extern "C" void kernel_launch(void* const* d_in, const int* in_sizes, int n_in,
                              void* d_out, int out_size) {
    const float* inputs  = (const float*)d_in[0];
    const float* hidden0 = (const float*)d_in[1];
    const float* actions = (const float*)d_in[2];
    const float* reward  = (const float*)d_in[3];
    const float* i2h     = (const float*)d_in[4];
    const float* h2h     = (const float*)d_in[5];
    const float* a2h     = (const float*)d_in[6];
    const float* r2h     = (const float*)d_in[7];
    const float* bh      = (const float*)d_in[8];
    const float* r       = (const float*)d_in[9];
    const void*  kact    = d_in[10];
    float* out = (float*)d_out;

    static int attr_done = 0;
    if (!attr_done) {
        cudaFuncSetAttribute(rnn_persistent,
                             cudaFuncAttributeMaxDynamicSharedMemorySize, SMEM_P_BYTES);
        attr_done = 1;
    }

    rbias_kernel<<<(B_DIM * H_DIM) / 256, 256>>>(reward, r2h, bh);
    wprep_kernel<<<dim3(32, 32), 256>>>(h2h);
    conv_h0_kernel<<<(B_DIM * H_DIM) / 256, 256>>>(hidden0);
    zero_rdy_kernel<<<8, 1024>>>();

    pre_kernel<<<(T_DIM / 64) * B_DIM, 256>>>(inputs, actions, i2h, a2h, kact, out);

    rnn_persistent<<<GRID_P, 256, SMEM_P_BYTES>>>(hidden0, r, out);
}

// round 15
// speedup vs baseline: 1.3187x; 1.3187x over previous
#include <cuda_runtime.h>
#include <cuda_bf16.h>
#include <cstdint>
#include <math.h>

// Problem constants
#define T_DIM 256
#define B_DIM 256
#define I_DIM 9
#define H_DIM 1024
#define A_DIM 4
#define R_DIM 38

#define GRID_P 128          // persistent grid: 4 M-tiles x 32 N-tiles

// ---------------------------------------------------------------------------
// Device scratch
// ---------------------------------------------------------------------------
__device__ float          g_rbias[B_DIM * H_DIM];
__device__ __nv_bfloat16  g_Whi[H_DIM * H_DIM];          // [N][K] hi
__device__ __nv_bfloat16  g_Wlo[H_DIM * H_DIM];          // [N][K] lo
__device__ __nv_bfloat16  g_A[2][B_DIM * 2 * H_DIM];     // hidden hi|lo ping-pong
__device__ unsigned       g_rdy[T_DIM * 4 * 8];          // dataflow counters

// ---------------------------------------------------------------------------
// Prep kernels
// ---------------------------------------------------------------------------
__global__ void rbias_kernel(const float* __restrict__ reward,
                             const float* __restrict__ r2h,
                             const float* __restrict__ bh) {
    int idx = blockIdx.x * blockDim.x + threadIdx.x;
    int h = idx & (H_DIM - 1);
    int b = idx >> 10;
    float s = bh[h];
    const float* rw = reward + b * R_DIM;
#pragma unroll
    for (int j = 0; j < R_DIM; ++j)
        s = fmaf(rw[j], r2h[j * H_DIM + h], s);
    g_rbias[idx] = s;
}

__global__ void wprep_kernel(const float* __restrict__ h2h) {
    __shared__ float tile[32][33];
    const int k0 = blockIdx.x * 32;
    const int n0 = blockIdx.y * 32;
    const int tid = threadIdx.x;
#pragma unroll
    for (int it = 0; it < 4; ++it) {
        int e = it * 256 + tid;
        int kk = e >> 5, nn = e & 31;
        tile[kk][nn] = h2h[(size_t)(k0 + kk) * H_DIM + n0 + nn];
    }
    __syncthreads();
#pragma unroll
    for (int it = 0; it < 2; ++it) {
        int e = it * 256 + tid;
        int nn = e >> 4, pp = e & 15;
        float w0 = tile[2 * pp][nn];
        float w1 = tile[2 * pp + 1][nn];
        __nv_bfloat16 h0 = __float2bfloat16(w0);
        __nv_bfloat16 h1 = __float2bfloat16(w1);
        __nv_bfloat16 l0 = __float2bfloat16(w0 - __bfloat162float(h0));
        __nv_bfloat16 l1 = __float2bfloat16(w1 - __bfloat162float(h1));
        size_t o = (size_t)(n0 + nn) * H_DIM + k0 + 2 * pp;
        *(__nv_bfloat162*)&g_Whi[o] = __nv_bfloat162(h0, h1);
        *(__nv_bfloat162*)&g_Wlo[o] = __nv_bfloat162(l0, l1);
    }
}

__global__ void conv_h0_kernel(const float* __restrict__ hidden0) {
    int idx = blockIdx.x * blockDim.x + threadIdx.x;
    int h = idx & (H_DIM - 1);
    int b = idx >> 10;
    float v = hidden0[idx];
    __nv_bfloat16 hi = __float2bfloat16(v);
    __nv_bfloat16 lo = __float2bfloat16(v - __bfloat162float(hi));
    g_A[0][(size_t)b * 2048 + h]        = hi;
    g_A[0][(size_t)b * 2048 + 1024 + h] = lo;
}

__global__ void zero_rdy_kernel() {
    g_rdy[blockIdx.x * 1024 + threadIdx.x] = 0u;
}

__device__ __forceinline__ float decode_k(const void* p) {
    int iv = *(const int*)p;
    float fv = __int_as_float(iv);
    float af = fabsf(fv);
    if (af >= 1e-30f && af <= 1e30f) return fv;
    return (float)iv;
}

// pre v3: block = fixed b, 64 timesteps; weights live in registers per thread.
__global__ void __launch_bounds__(256)
pre_kernel(const float* __restrict__ inputs,
           const float* __restrict__ actions,
           const float* __restrict__ i2h,
           const float* __restrict__ a2h,
           const void*  __restrict__ kact_ptr,
           float* __restrict__ out) {
    __shared__ float sinA[64 * I_DIM];
    __shared__ float sactA[64 * A_DIM];
    __shared__ float sk;
    const int b  = blockIdx.x & (B_DIM - 1);
    const int t0 = (blockIdx.x >> 8) << 6;
    const int tid = threadIdx.x;

    for (int e = tid; e < 64 * I_DIM; e += 256) {
        int j = e / I_DIM, i = e - j * I_DIM;
        sinA[e] = inputs[((size_t)(t0 + j) * B_DIM + b) * I_DIM + i];
    }
    for (int e = tid; e < 64 * A_DIM; e += 256) {
        int j = e >> 2, a = e & 3;
        sactA[e] = actions[((size_t)(t0 + j) * B_DIM + b) * A_DIM + a];
    }
    if (tid == 0) sk = decode_k(kact_ptr);
    __syncthreads();

    const int h = tid * 4;
    float4 rb = *(const float4*)&g_rbias[b * H_DIM + h];
    float4 wi[I_DIM], wa[A_DIM];
#pragma unroll
    for (int i = 0; i < I_DIM; ++i) wi[i] = *(const float4*)&i2h[i * H_DIM + h];
#pragma unroll
    for (int a = 0; a < A_DIM; ++a) wa[a] = *(const float4*)&a2h[a * H_DIM + h];
    const float k = sk;

    for (int j = 0; j < 64; ++j) {
        float4 s = rb;
#pragma unroll
        for (int i = 0; i < I_DIM; ++i) {
            float x = sinA[j * I_DIM + i];
            s.x = fmaf(x, wi[i].x, s.x); s.y = fmaf(x, wi[i].y, s.y);
            s.z = fmaf(x, wi[i].z, s.z); s.w = fmaf(x, wi[i].w, s.w);
        }
#pragma unroll
        for (int a = 0; a < A_DIM; ++a) {
            float x = k * sactA[j * A_DIM + a];
            s.x = fmaf(x, wa[a].x, s.x); s.y = fmaf(x, wa[a].y, s.y);
            s.z = fmaf(x, wa[a].z, s.z); s.w = fmaf(x, wa[a].w, s.w);
        }
        *(float4*)&out[((size_t)(t0 + j) * B_DIM + b) * H_DIM + h] = s;
    }
}

// ---------------------------------------------------------------------------
// Persistent recurrence kernel (R12 base + split hi/lo accumulator chains)
// ---------------------------------------------------------------------------
__device__ __forceinline__ float tanh_fast(float x) {
    float e = __expf(2.0f * x);
    return 1.0f - __fdividef(2.0f, e + 1.0f);
}
__device__ __forceinline__ uint32_t smem_u32(const void* p) {
    uint32_t a;
    asm("{ .reg .u64 t; cvta.to.shared.u64 t, %1; cvt.u32.u64 %0, t; }" : "=r"(a) : "l"(p));
    return a;
}
__device__ __forceinline__ unsigned ld_acq(const unsigned* p) {
    unsigned v;
    asm volatile("ld.acquire.gpu.global.u32 %0, [%1];" : "=r"(v) : "l"(p) : "memory");
    return v;
}
#define CP_ASYNC16(dst, src) \
    asm volatile("cp.async.cg.shared.global [%0], [%1], 16;" :: "r"(dst), "l"(src))
#define CP_COMMIT() asm volatile("cp.async.commit_group;" ::: "memory")
#define CP_WAIT(n)  asm volatile("cp.async.wait_group %0;" :: "n"(n) : "memory")

__device__ __forceinline__ void mma16816(float* c, const uint32_t* a, const uint32_t* b) {
    asm volatile(
        "mma.sync.aligned.m16n8k16.row.col.f32.bf16.bf16.f32 "
        "{%0,%1,%2,%3}, {%4,%5,%6,%7}, {%8,%9}, {%0,%1,%2,%3};"
        : "+f"(c[0]), "+f"(c[1]), "+f"(c[2]), "+f"(c[3])
        : "r"(a[0]), "r"(a[1]), "r"(a[2]), "r"(a[3]), "r"(b[0]), "r"(b[1]));
}
__device__ __forceinline__ void ldsm4(uint32_t* r, uint32_t addr) {
    asm volatile("ldmatrix.sync.aligned.m8n8.x4.shared.b16 {%0,%1,%2,%3}, [%4];"
        : "=r"(r[0]), "=r"(r[1]), "=r"(r[2]), "=r"(r[3]) : "r"(addr));
}

// smem words: Whi[32][516] @0, Wlo @16512, A ring: 4 bufs of 64x68 @33024
#define WS_STRIDE 516
#define WLO_OFF   16512
#define ABUF_OFF  33024
#define ABUF_SZ   4352
#define A_STRIDE  68
#define SMEM_P_WORDS (ABUF_OFF + 4 * ABUF_SZ)        // 50432
#define SMEM_P_BYTES (SMEM_P_WORDS * 4)              // 201728
#define NCHUNK 16

__global__ void __launch_bounds__(256, 1)
rnn_persistent(const float* __restrict__ hidden0,
               const float* __restrict__ rr,
               float* __restrict__ out) {
    extern __shared__ uint32_t smw[];
    const int tid  = threadIdx.x;
    const int wid  = tid >> 5;
    const int lane = tid & 31;
    const int gid  = lane >> 2;
    const int tig  = lane & 3;
    const int wm   = wid >> 1;           // 0..3 (16-row slabs)
    const int wn   = wid & 1;            // 0..1 (16-col slabs)
    const int n_grp = blockIdx.x & 31;
    const int m_grp = blockIdx.x >> 5;
    const int m0 = m_grp * 64;
    const int n0 = n_grp * 32;

    // ---- W slice (hi+lo) into smem once ----
    for (int e = tid; e < 32 * 128; e += 256) {
        int n = e >> 7, c = e & 127;
        uint4 vh = *(const uint4*)&g_Whi[(size_t)(n0 + n) * H_DIM + c * 8];
        uint4 vl = *(const uint4*)&g_Wlo[(size_t)(n0 + n) * H_DIM + c * 8];
        *(uint4*)&smw[n * WS_STRIDE + c * 4]           = vh;
        *(uint4*)&smw[WLO_OFF + n * WS_STRIDE + c * 4] = vl;
    }

    // ---- prev hidden tile + inertia in registers ----
    float hprev[2][4];
    float2 rv[2];
#pragma unroll
    for (int nt = 0; nt < 2; ++nt) {
        int c = n0 + wn * 16 + nt * 8 + tig * 2;
        rv[nt] = *(const float2*)&rr[c];
#pragma unroll
        for (int half = 0; half < 2; ++half) {
            int row = m0 + wm * 16 + gid + half * 8;
            float2 hp = *(const float2*)&hidden0[(size_t)row * H_DIM + c];
            hprev[nt][half * 2]     = hp.x;
            hprev[nt][half * 2 + 1] = hp.y;
        }
    }

    // ldmatrix lane word-offsets (fixed)
    const uint32_t sbase = smem_u32(smw);
    const int a_lane_off = (wm * 16 + (lane & 15)) * A_STRIDE + ((lane >> 4) << 2);
    const int b_lane_row = wn * 16 + (lane & 7) + ((lane >> 4) << 3);
    const int b_lane_off = b_lane_row * WS_STRIDE + (((lane >> 3) & 1) << 2);

    __syncthreads();

    for (int t = 0; t < T_DIM; ++t) {
        const __nv_bfloat16* __restrict__ A     = g_A[t & 1];
        __nv_bfloat16* __restrict__       Anext = g_A[(t + 1) & 1];
        float* __restrict__ outt = out + (size_t)t * (B_DIM * H_DIM);

        // independent hi/lo accumulator chains (summed in epilogue)
        float acch[2][4], accl[2][4];
#pragma unroll
        for (int nt = 0; nt < 2; ++nt)
#pragma unroll
            for (int q = 0; q < 4; ++q) { acch[nt][q] = 0.f; accl[nt][q] = 0.f; }

        // Prefetch pre tile into registers (hidden under the GEMM)
        float2 pre_r[2][2];
#pragma unroll
        for (int nt = 0; nt < 2; ++nt) {
            const int c = n0 + wn * 16 + nt * 8 + tig * 2;
#pragma unroll
            for (int half = 0; half < 2; ++half) {
                const int row = m0 + wm * 16 + gid + half * 8;
                pre_r[nt][half] = *(const float2*)(outt + (size_t)row * H_DIM + c);
            }
        }

        // dataflow wait: chunk c (c<8) gated by 4 producers of its 128-col group
        auto wait_c = [&](int c) {
            if (t == 0 || c >= 8) return;
            const unsigned* p = &g_rdy[((t << 2) + m_grp) * 8 + c];
            while (ld_acq(p) < 4u) __nanosleep(40);
        };
        // chunk c: c<8 -> A-hi 128-col block c (vs Whi AND Wlo); c>=8 -> A-lo (vs Whi)
        auto issue = [&](int c) {
            const int buf = c & 3;
            const __nv_bfloat16* Ab = A + (size_t)m0 * 2048
                                        + ((c >= 8) ? 1024 : 0) + ((c & 7) << 7);
            const uint32_t base = sbase + (uint32_t)(ABUF_OFF + buf * ABUF_SZ) * 4;
#pragma unroll
            for (int j = 0; j < 4; ++j) {
                int idx = tid + (j << 8);
                int row = idx >> 4, seg = idx & 15;
                CP_ASYNC16(base + (uint32_t)(row * A_STRIDE + seg * 4) * 4,
                           (const void*)(Ab + (size_t)row * 2048 + seg * 8));
            }
            CP_COMMIT();
        };

        // MMA over one chunk held in buffer (c&3)
        auto mma_chunk = [&](int c) {
            const int abuf_w = ABUF_OFF + (c & 3) * ABUF_SZ;
            const int kw = (c & 7) << 6;           // chunk word offset in W rows
            const bool hi = (c < 8);
#pragma unroll
            for (int k16 = 0; k16 < 8; ++k16) {
                uint32_t af[4];
                ldsm4(af, sbase + (uint32_t)(abuf_w + a_lane_off + k16 * 8) * 4);
                const int kb = kw + k16 * 8;
                uint32_t bh_[4];
                ldsm4(bh_, sbase + (uint32_t)(b_lane_off + kb) * 4);
                if (hi) {
                    uint32_t bl_[4];
                    ldsm4(bl_, sbase + (uint32_t)(WLO_OFF + b_lane_off + kb) * 4);
                    mma16816(acch[0], af, bh_);
                    mma16816(acch[1], af, bh_ + 2);
                    mma16816(accl[0], af, bl_);
                    mma16816(accl[1], af, bl_ + 2);
                } else {
                    mma16816(acch[0], af, bh_);
                    mma16816(acch[1], af, bh_ + 2);
                }
            }
        };

        wait_c(0); issue(0);
        wait_c(1); issue(1);
        wait_c(2); issue(2);
        wait_c(3); issue(3);

        // paired chunks: one wait+sync per 2 chunks (8 syncs/step)
        for (int p = 0; p < NCHUNK / 2; ++p) {
            if (p < NCHUNK / 2 - 1) { CP_WAIT(2); } else { CP_WAIT(0); }
            __syncthreads();
            mma_chunk(2 * p);
            mma_chunk(2 * p + 1);
            if (2 * p + 4 < NCHUNK) {
                int c = 2 * p + 4;
                wait_c(c);     issue(c);
                wait_c(c + 1); issue(c + 1);
            }
        }

        // ---- epilogue: combine chains, tanh + blend; publish Anext; release ----
#pragma unroll
        for (int nt = 0; nt < 2; ++nt) {
            const int c = n0 + wn * 16 + nt * 8 + tig * 2;
#pragma unroll
            for (int half = 0; half < 2; ++half) {
                const int row = m0 + wm * 16 + gid + half * 8;
                const float ax = acch[nt][half * 2]     + accl[nt][half * 2];
                const float ay = acch[nt][half * 2 + 1] + accl[nt][half * 2 + 1];
                float tt, h0, h1;
                tt = tanh_fast(pre_r[nt][half].x + ax);
                h0 = tt + rv[nt].x * (hprev[nt][half * 2] - tt);
                tt = tanh_fast(pre_r[nt][half].y + ay);
                h1 = tt + rv[nt].y * (hprev[nt][half * 2 + 1] - tt);
                hprev[nt][half * 2]     = h0;
                hprev[nt][half * 2 + 1] = h1;

                if (t < T_DIM - 1) {
                    __nv_bfloat16 a0 = __float2bfloat16(h0);
                    __nv_bfloat16 a1 = __float2bfloat16(h1);
                    __nv_bfloat16* hip = Anext + (size_t)row * 2048 + c;
                    *(__nv_bfloat162*)hip = __nv_bfloat162(a0, a1);
                    __nv_bfloat16 l0 = __float2bfloat16(h0 - __bfloat162float(a0));
                    __nv_bfloat16 l1 = __float2bfloat16(h1 - __bfloat162float(a1));
                    *(__nv_bfloat162*)(hip + 1024) = __nv_bfloat162(l0, l1);
                }
            }
        }

        if (t < T_DIM - 1) {
            __threadfence();
            __syncthreads();
            if (tid == 0) {
                asm volatile("red.release.gpu.global.add.u32 [%0], 1;"
                    :: "l"(&g_rdy[(((t + 1) << 2) + m_grp) * 8 + (n_grp >> 2)])
                    : "memory");
            }
        }

        // deferred fp32 out store (off the inter-CTA critical path)
#pragma unroll
        for (int nt = 0; nt < 2; ++nt) {
            const int c = n0 + wn * 16 + nt * 8 + tig * 2;
#pragma unroll
            for (int half = 0; half < 2; ++half) {
                const int row = m0 + wm * 16 + gid + half * 8;
                *(float2*)(outt + (size_t)row * H_DIM + c) =
                    make_float2(hprev[nt][half * 2], hprev[nt][half * 2 + 1]);
            }
        }
    }
}

// ---------------------------------------------------------------------------
// Launch
// ---------------------------------------------------------------------------
extern "C" void kernel_launch(void* const* d_in, const int* in_sizes, int n_in,
                              void* d_out, int out_size) {
    const float* inputs  = (const float*)d_in[0];
    const float* hidden0 = (const float*)d_in[1];
    const float* actions = (const float*)d_in[2];
    const float* reward  = (const float*)d_in[3];
    const float* i2h     = (const float*)d_in[4];
    const float* h2h     = (const float*)d_in[5];
    const float* a2h     = (const float*)d_in[6];
    const float* r2h     = (const float*)d_in[7];
    const float* bh      = (const float*)d_in[8];
    const float* r       = (const float*)d_in[9];
    const void*  kact    = d_in[10];
    float* out = (float*)d_out;

    static int attr_done = 0;
    if (!attr_done) {
        cudaFuncSetAttribute(rnn_persistent,
                             cudaFuncAttributeMaxDynamicSharedMemorySize, SMEM_P_BYTES);
        attr_done = 1;
    }

    rbias_kernel<<<(B_DIM * H_DIM) / 256, 256>>>(reward, r2h, bh);
    wprep_kernel<<<dim3(32, 32), 256>>>(h2h);
    conv_h0_kernel<<<(B_DIM * H_DIM) / 256, 256>>>(hidden0);
    zero_rdy_kernel<<<8, 1024>>>();

    pre_kernel<<<(T_DIM / 64) * B_DIM, 256>>>(inputs, actions, i2h, a2h, kact, out);

    rnn_persistent<<<GRID_P, 256, SMEM_P_BYTES>>>(hidden0, r, out);
}

// round 16
// speedup vs baseline: 1.5637x; 1.1858x over previous
#include <cuda_runtime.h>
#include <cuda_bf16.h>
#include <cstdint>
#include <math.h>

// Problem constants
#define T_DIM 256
#define B_DIM 256
#define I_DIM 9
#define H_DIM 1024
#define A_DIM 4
#define R_DIM 38

#define GRID_P 128          // persistent grid: 4 M-tiles x 32 N-tiles

// ---------------------------------------------------------------------------
// Device scratch
// ---------------------------------------------------------------------------
__device__ float          g_rbias[B_DIM * H_DIM];
__device__ __nv_bfloat16  g_Whi[H_DIM * H_DIM];          // [N][K] hi
__device__ __nv_bfloat16  g_Wlo[H_DIM * H_DIM];          // [N][K] lo
__device__ __nv_bfloat16  g_A[2][B_DIM * 2 * H_DIM];     // hidden hi|lo ping-pong
__device__ unsigned       g_rdy[T_DIM * 4 * 8];          // dataflow counters

__device__ __forceinline__ float decode_k(const void* p) {
    int iv = *(const int*)p;
    float fv = __int_as_float(iv);
    float af = fabsf(fv);
    if (af >= 1e-30f && af <= 1e30f) return fv;
    return (float)iv;
}

// ---------------------------------------------------------------------------
// Fused prep kernel: block-range dispatch.
//   [0,1024)      rbias = reward @ r2h + bh
//   [1024,2048)   W transpose + hi/lo split
//   [2048,3072)   hidden0 -> g_A[0]
//   [3072,3104)   zero g_rdy
// ---------------------------------------------------------------------------
__global__ void __launch_bounds__(256)
prep_kernel(const float* __restrict__ reward,
            const float* __restrict__ r2h,
            const float* __restrict__ bh,
            const float* __restrict__ h2h,
            const float* __restrict__ hidden0) {
    const int bx = blockIdx.x;
    const int tid = threadIdx.x;

    if (bx < 1024) {                       // ---- rbias ----
        int idx = bx * 256 + tid;
        int h = idx & (H_DIM - 1);
        int b = idx >> 10;
        float s = bh[h];
        const float* rw = reward + b * R_DIM;
#pragma unroll
        for (int j = 0; j < R_DIM; ++j)
            s = fmaf(rw[j], r2h[j * H_DIM + h], s);
        g_rbias[idx] = s;
    } else if (bx < 2048) {                // ---- W prep ----
        __shared__ float tile[32][33];
        const int e0 = bx - 1024;
        const int k0 = (e0 & 31) * 32;
        const int n0 = (e0 >> 5) * 32;
#pragma unroll
        for (int it = 0; it < 4; ++it) {
            int e = it * 256 + tid;
            int kk = e >> 5, nn = e & 31;
            tile[kk][nn] = h2h[(size_t)(k0 + kk) * H_DIM + n0 + nn];
        }
        __syncthreads();
#pragma unroll
        for (int it = 0; it < 2; ++it) {
            int e = it * 256 + tid;
            int nn = e >> 4, pp = e & 15;
            float w0 = tile[2 * pp][nn];
            float w1 = tile[2 * pp + 1][nn];
            __nv_bfloat16 h0 = __float2bfloat16(w0);
            __nv_bfloat16 h1 = __float2bfloat16(w1);
            __nv_bfloat16 l0 = __float2bfloat16(w0 - __bfloat162float(h0));
            __nv_bfloat16 l1 = __float2bfloat16(w1 - __bfloat162float(h1));
            size_t o = (size_t)(n0 + nn) * H_DIM + k0 + 2 * pp;
            *(__nv_bfloat162*)&g_Whi[o] = __nv_bfloat162(h0, h1);
            *(__nv_bfloat162*)&g_Wlo[o] = __nv_bfloat162(l0, l1);
        }
    } else if (bx < 3072) {                // ---- conv h0 ----
        int idx = (bx - 2048) * 256 + tid;
        int h = idx & (H_DIM - 1);
        int b = idx >> 10;
        float v = hidden0[idx];
        __nv_bfloat16 hi = __float2bfloat16(v);
        __nv_bfloat16 lo = __float2bfloat16(v - __bfloat162float(hi));
        g_A[0][(size_t)b * 2048 + h]        = hi;
        g_A[0][(size_t)b * 2048 + 1024 + h] = lo;
    } else {                               // ---- zero rdy ----
        g_rdy[(bx - 3072) * 256 + tid] = 0u;
    }
}

// pre v3: block = fixed b, 64 timesteps; weights live in registers per thread.
__global__ void __launch_bounds__(256)
pre_kernel(const float* __restrict__ inputs,
           const float* __restrict__ actions,
           const float* __restrict__ i2h,
           const float* __restrict__ a2h,
           const void*  __restrict__ kact_ptr,
           float* __restrict__ out) {
    __shared__ float sinA[64 * I_DIM];
    __shared__ float sactA[64 * A_DIM];
    __shared__ float sk;
    const int b  = blockIdx.x & (B_DIM - 1);
    const int t0 = (blockIdx.x >> 8) << 6;
    const int tid = threadIdx.x;

    for (int e = tid; e < 64 * I_DIM; e += 256) {
        int j = e / I_DIM, i = e - j * I_DIM;
        sinA[e] = inputs[((size_t)(t0 + j) * B_DIM + b) * I_DIM + i];
    }
    for (int e = tid; e < 64 * A_DIM; e += 256) {
        int j = e >> 2, a = e & 3;
        sactA[e] = actions[((size_t)(t0 + j) * B_DIM + b) * A_DIM + a];
    }
    if (tid == 0) sk = decode_k(kact_ptr);
    __syncthreads();

    const int h = tid * 4;
    float4 rb = *(const float4*)&g_rbias[b * H_DIM + h];
    float4 wi[I_DIM], wa[A_DIM];
#pragma unroll
    for (int i = 0; i < I_DIM; ++i) wi[i] = *(const float4*)&i2h[i * H_DIM + h];
#pragma unroll
    for (int a = 0; a < A_DIM; ++a) wa[a] = *(const float4*)&a2h[a * H_DIM + h];
    const float k = sk;

    for (int j = 0; j < 64; ++j) {
        float4 s = rb;
#pragma unroll
        for (int i = 0; i < I_DIM; ++i) {
            float x = sinA[j * I_DIM + i];
            s.x = fmaf(x, wi[i].x, s.x); s.y = fmaf(x, wi[i].y, s.y);
            s.z = fmaf(x, wi[i].z, s.z); s.w = fmaf(x, wi[i].w, s.w);
        }
#pragma unroll
        for (int a = 0; a < A_DIM; ++a) {
            float x = k * sactA[j * A_DIM + a];
            s.x = fmaf(x, wa[a].x, s.x); s.y = fmaf(x, wa[a].y, s.y);
            s.z = fmaf(x, wa[a].z, s.z); s.w = fmaf(x, wa[a].w, s.w);
        }
        *(float4*)&out[((size_t)(t0 + j) * B_DIM + b) * H_DIM + h] = s;
    }
}

// ---------------------------------------------------------------------------
// Persistent recurrence kernel (R12 base + paired hi/lo chunks for B reuse)
// ---------------------------------------------------------------------------
__device__ __forceinline__ float tanh_fast(float x) {
    float e = __expf(2.0f * x);
    return 1.0f - __fdividef(2.0f, e + 1.0f);
}
__device__ __forceinline__ uint32_t smem_u32(const void* p) {
    uint32_t a;
    asm("{ .reg .u64 t; cvta.to.shared.u64 t, %1; cvt.u32.u64 %0, t; }" : "=r"(a) : "l"(p));
    return a;
}
__device__ __forceinline__ unsigned ld_acq(const unsigned* p) {
    unsigned v;
    asm volatile("ld.acquire.gpu.global.u32 %0, [%1];" : "=r"(v) : "l"(p) : "memory");
    return v;
}
#define CP_ASYNC16(dst, src) \
    asm volatile("cp.async.cg.shared.global [%0], [%1], 16;" :: "r"(dst), "l"(src))
#define CP_COMMIT() asm volatile("cp.async.commit_group;" ::: "memory")
#define CP_WAIT(n)  asm volatile("cp.async.wait_group %0;" :: "n"(n) : "memory")

__device__ __forceinline__ void mma16816(float* c, const uint32_t* a, const uint32_t* b) {
    asm volatile(
        "mma.sync.aligned.m16n8k16.row.col.f32.bf16.bf16.f32 "
        "{%0,%1,%2,%3}, {%4,%5,%6,%7}, {%8,%9}, {%0,%1,%2,%3};"
        : "+f"(c[0]), "+f"(c[1]), "+f"(c[2]), "+f"(c[3])
        : "r"(a[0]), "r"(a[1]), "r"(a[2]), "r"(a[3]), "r"(b[0]), "r"(b[1]));
}
__device__ __forceinline__ void ldsm4(uint32_t* r, uint32_t addr) {
    asm volatile("ldmatrix.sync.aligned.m8n8.x4.shared.b16 {%0,%1,%2,%3}, [%4];"
        : "=r"(r[0]), "=r"(r[1]), "=r"(r[2]), "=r"(r[3]) : "r"(addr));
}

// smem words: Whi[32][516] @0, Wlo @16512, A ring: 4 bufs of 64x68 @33024
#define WS_STRIDE 516
#define WLO_OFF   16512
#define ABUF_OFF  33024
#define ABUF_SZ   4352
#define A_STRIDE  68
#define SMEM_P_WORDS (ABUF_OFF + 4 * ABUF_SZ)        // 50432
#define SMEM_P_BYTES (SMEM_P_WORDS * 4)              // 201728
#define NSEQ 16

__global__ void __launch_bounds__(256, 1)
rnn_persistent(const float* __restrict__ hidden0,
               const float* __restrict__ rr,
               float* __restrict__ out) {
    extern __shared__ uint32_t smw[];
    const int tid  = threadIdx.x;
    const int wid  = tid >> 5;
    const int lane = tid & 31;
    const int gid  = lane >> 2;
    const int tig  = lane & 3;
    const int wm   = wid >> 1;           // 0..3 (16-row slabs)
    const int wn   = wid & 1;            // 0..1 (16-col slabs)
    const int n_grp = blockIdx.x & 31;
    const int m_grp = blockIdx.x >> 5;
    const int m0 = m_grp * 64;
    const int n0 = n_grp * 32;

    // ---- W slice (hi+lo) into smem once ----
    for (int e = tid; e < 32 * 128; e += 256) {
        int n = e >> 7, c = e & 127;
        uint4 vh = *(const uint4*)&g_Whi[(size_t)(n0 + n) * H_DIM + c * 8];
        uint4 vl = *(const uint4*)&g_Wlo[(size_t)(n0 + n) * H_DIM + c * 8];
        *(uint4*)&smw[n * WS_STRIDE + c * 4]           = vh;
        *(uint4*)&smw[WLO_OFF + n * WS_STRIDE + c * 4] = vl;
    }

    // ---- prev hidden tile + inertia in registers ----
    float hprev[2][4];
    float2 rv[2];
#pragma unroll
    for (int nt = 0; nt < 2; ++nt) {
        int c = n0 + wn * 16 + nt * 8 + tig * 2;
        rv[nt] = *(const float2*)&rr[c];
#pragma unroll
        for (int half = 0; half < 2; ++half) {
            int row = m0 + wm * 16 + gid + half * 8;
            float2 hp = *(const float2*)&hidden0[(size_t)row * H_DIM + c];
            hprev[nt][half * 2]     = hp.x;
            hprev[nt][half * 2 + 1] = hp.y;
        }
    }

    // ldmatrix lane word-offsets (fixed)
    const uint32_t sbase = smem_u32(smw);
    const int a_lane_off = (wm * 16 + (lane & 15)) * A_STRIDE + ((lane >> 4) << 2);
    const int b_lane_row = wn * 16 + (lane & 7) + ((lane >> 4) << 3);
    const int b_lane_off = b_lane_row * WS_STRIDE + (((lane >> 3) & 1) << 2);

    __syncthreads();

    for (int t = 0; t < T_DIM; ++t) {
        const __nv_bfloat16* __restrict__ A     = g_A[t & 1];
        __nv_bfloat16* __restrict__       Anext = g_A[(t + 1) & 1];
        float* __restrict__ outt = out + (size_t)t * (B_DIM * H_DIM);

        float acc[2][4];
#pragma unroll
        for (int nt = 0; nt < 2; ++nt)
#pragma unroll
            for (int q = 0; q < 4; ++q) acc[nt][q] = 0.f;

        // Prefetch pre tile into registers (hidden under the GEMM)
        float2 pre_r[2][2];
#pragma unroll
        for (int nt = 0; nt < 2; ++nt) {
            const int c = n0 + wn * 16 + nt * 8 + tig * 2;
#pragma unroll
            for (int half = 0; half < 2; ++half) {
                const int row = m0 + wm * 16 + gid + half * 8;
                pre_r[nt][half] = *(const float2*)(outt + (size_t)row * H_DIM + c);
            }
        }

        // dataflow wait: 128-col group g gated by its 4 producers
        auto wait_g = [&](int g) {
            if (t == 0) return;
            const unsigned* p = &g_rdy[((t << 2) + m_grp) * 8 + g];
            while (ld_acq(p) < 4u) __nanosleep(40);
        };
        // sequence j: even -> A-hi col-group j/2; odd -> A-lo col-group j/2.
        // Buffer = j & 3.
        auto issue = [&](int j) {
            const int grp = j >> 1;
            const __nv_bfloat16* Ab = A + (size_t)m0 * 2048
                                        + ((j & 1) ? 1024 : 0) + (grp << 7);
            const uint32_t base = sbase + (uint32_t)(ABUF_OFF + (j & 3) * ABUF_SZ) * 4;
#pragma unroll
            for (int q = 0; q < 4; ++q) {
                int idx = tid + (q << 8);
                int row = idx >> 4, seg = idx & 15;
                CP_ASYNC16(base + (uint32_t)(row * A_STRIDE + seg * 4) * 4,
                           (const void*)(Ab + (size_t)row * 2048 + seg * 8));
            }
            CP_COMMIT();
        };

        // paired MMA: hi buf (seq 2p) + lo buf (seq 2p+1), shared bh fragments
        auto mma_pair = [&](int p) {
            const int abuf_h = ABUF_OFF + ((2 * p) & 3) * ABUF_SZ;
            const int abuf_l = ABUF_OFF + ((2 * p + 1) & 3) * ABUF_SZ;
            const int kw = p << 6;               // col-group word offset in W rows
#pragma unroll
            for (int k16 = 0; k16 < 8; ++k16) {
                const int ao = k16 * 8;
                const int kb = kw + k16 * 8;
                uint32_t af_h[4], af_l[4], bh_[4], bl_[4];
                ldsm4(af_h, sbase + (uint32_t)(abuf_h + a_lane_off + ao) * 4);
                ldsm4(bh_,  sbase + (uint32_t)(b_lane_off + kb) * 4);
                ldsm4(af_l, sbase + (uint32_t)(abuf_l + a_lane_off + ao) * 4);
                ldsm4(bl_,  sbase + (uint32_t)(WLO_OFF + b_lane_off + kb) * 4);
                mma16816(acc[0], af_h, bh_);
                mma16816(acc[1], af_h, bh_ + 2);
                mma16816(acc[0], af_h, bl_);
                mma16816(acc[1], af_h, bl_ + 2);
                mma16816(acc[0], af_l, bh_);
                mma16816(acc[1], af_l, bh_ + 2);
            }
        };

        wait_g(0); issue(0); issue(1);
        wait_g(1); issue(2); issue(3);

        for (int p = 0; p < NSEQ / 2; ++p) {
            if (p < NSEQ / 2 - 1) { CP_WAIT(2); } else { CP_WAIT(0); }
            __syncthreads();
            mma_pair(p);
            if (2 * p + 4 < NSEQ) {
                wait_g(p + 2);
                issue(2 * p + 4);
                issue(2 * p + 5);
            }
        }

        // ---- epilogue: tanh + blend; publish Anext; release; then out STG ----
#pragma unroll
        for (int nt = 0; nt < 2; ++nt) {
            const int c = n0 + wn * 16 + nt * 8 + tig * 2;
#pragma unroll
            for (int half = 0; half < 2; ++half) {
                const int row = m0 + wm * 16 + gid + half * 8;
                float tt, h0, h1;
                tt = tanh_fast(pre_r[nt][half].x + acc[nt][half * 2]);
                h0 = tt + rv[nt].x * (hprev[nt][half * 2] - tt);
                tt = tanh_fast(pre_r[nt][half].y + acc[nt][half * 2 + 1]);
                h1 = tt + rv[nt].y * (hprev[nt][half * 2 + 1] - tt);
                hprev[nt][half * 2]     = h0;
                hprev[nt][half * 2 + 1] = h1;

                if (t < T_DIM - 1) {
                    __nv_bfloat16 a0 = __float2bfloat16(h0);
                    __nv_bfloat16 a1 = __float2bfloat16(h1);
                    __nv_bfloat16* hip = Anext + (size_t)row * 2048 + c;
                    *(__nv_bfloat162*)hip = __nv_bfloat162(a0, a1);
                    __nv_bfloat16 l0 = __float2bfloat16(h0 - __bfloat162float(a0));
                    __nv_bfloat16 l1 = __float2bfloat16(h1 - __bfloat162float(a1));
                    *(__nv_bfloat162*)(hip + 1024) = __nv_bfloat162(l0, l1);
                }
            }
        }

        if (t < T_DIM - 1) {
            __threadfence();
            __syncthreads();
            if (tid == 0) {
                asm volatile("red.release.gpu.global.add.u32 [%0], 1;"
                    :: "l"(&g_rdy[(((t + 1) << 2) + m_grp) * 8 + (n_grp >> 2)])
                    : "memory");
            }
        }

        // deferred fp32 out store (off the inter-CTA critical path)
#pragma unroll
        for (int nt = 0; nt < 2; ++nt) {
            const int c = n0 + wn * 16 + nt * 8 + tig * 2;
#pragma unroll
            for (int half = 0; half < 2; ++half) {
                const int row = m0 + wm * 16 + gid + half * 8;
                *(float2*)(outt + (size_t)row * H_DIM + c) =
                    make_float2(hprev[nt][half * 2], hprev[nt][half * 2 + 1]);
            }
        }
    }
}

// ---------------------------------------------------------------------------
// Launch: prep -> pre -> persistent (3 launches, graph-capturable)
// ---------------------------------------------------------------------------
extern "C" void kernel_launch(void* const* d_in, const int* in_sizes, int n_in,
                              void* d_out, int out_size) {
    const float* inputs  = (const float*)d_in[0];
    const float* hidden0 = (const float*)d_in[1];
    const float* actions = (const float*)d_in[2];
    const float* reward  = (const float*)d_in[3];
    const float* i2h     = (const float*)d_in[4];
    const float* h2h     = (const float*)d_in[5];
    const float* a2h     = (const float*)d_in[6];
    const float* r2h     = (const float*)d_in[7];
    const float* bh      = (const float*)d_in[8];
    const float* r       = (const float*)d_in[9];
    const void*  kact    = d_in[10];
    float* out = (float*)d_out;

    static int attr_done = 0;
    if (!attr_done) {
        cudaFuncSetAttribute(rnn_persistent,
                             cudaFuncAttributeMaxDynamicSharedMemorySize, SMEM_P_BYTES);
        attr_done = 1;
    }

    prep_kernel<<<3104, 256>>>(reward, r2h, bh, h2h, hidden0);
    pre_kernel<<<(T_DIM / 64) * B_DIM, 256>>>(inputs, actions, i2h, a2h, kact, out);
    rnn_persistent<<<GRID_P, 256, SMEM_P_BYTES>>>(hidden0, r, out);
}

// round 17
// speedup vs baseline: 1.5647x; 1.0006x over previous
#include <cuda_runtime.h>
#include <cuda_bf16.h>
#include <cstdint>
#include <math.h>

// Problem constants
#define T_DIM 256
#define B_DIM 256
#define I_DIM 9
#define H_DIM 1024
#define A_DIM 4
#define R_DIM 38

#define GRID_P 128          // persistent grid: 4 M-tiles x 32 N-tiles

// ---------------------------------------------------------------------------
// Device scratch
// ---------------------------------------------------------------------------
__device__ float          g_rbias[B_DIM * H_DIM];
__device__ __nv_bfloat16  g_Whi[H_DIM * H_DIM];          // [N][K] hi
__device__ __nv_bfloat16  g_Wlo[H_DIM * H_DIM];          // [N][K] lo
__device__ __nv_bfloat16  g_A[2][B_DIM * 2 * H_DIM];     // hidden hi|lo ping-pong
__device__ unsigned       g_rdy[T_DIM * 4 * 8];          // dataflow counters

__device__ __forceinline__ float decode_k(const void* p) {
    int iv = *(const int*)p;
    float fv = __int_as_float(iv);
    float af = fabsf(fv);
    if (af >= 1e-30f && af <= 1e30f) return fv;
    return (float)iv;
}

// ---------------------------------------------------------------------------
// Fused prep kernel: block-range dispatch.
// ---------------------------------------------------------------------------
__global__ void __launch_bounds__(256)
prep_kernel(const float* __restrict__ reward,
            const float* __restrict__ r2h,
            const float* __restrict__ bh,
            const float* __restrict__ h2h,
            const float* __restrict__ hidden0) {
    const int bx = blockIdx.x;
    const int tid = threadIdx.x;

    if (bx < 1024) {                       // ---- rbias ----
        int idx = bx * 256 + tid;
        int h = idx & (H_DIM - 1);
        int b = idx >> 10;
        float s = bh[h];
        const float* rw = reward + b * R_DIM;
#pragma unroll
        for (int j = 0; j < R_DIM; ++j)
            s = fmaf(rw[j], r2h[j * H_DIM + h], s);
        g_rbias[idx] = s;
    } else if (bx < 2048) {                // ---- W prep ----
        __shared__ float tile[32][33];
        const int e0 = bx - 1024;
        const int k0 = (e0 & 31) * 32;
        const int n0 = (e0 >> 5) * 32;
#pragma unroll
        for (int it = 0; it < 4; ++it) {
            int e = it * 256 + tid;
            int kk = e >> 5, nn = e & 31;
            tile[kk][nn] = h2h[(size_t)(k0 + kk) * H_DIM + n0 + nn];
        }
        __syncthreads();
#pragma unroll
        for (int it = 0; it < 2; ++it) {
            int e = it * 256 + tid;
            int nn = e >> 4, pp = e & 15;
            float w0 = tile[2 * pp][nn];
            float w1 = tile[2 * pp + 1][nn];
            __nv_bfloat16 h0 = __float2bfloat16(w0);
            __nv_bfloat16 h1 = __float2bfloat16(w1);
            __nv_bfloat16 l0 = __float2bfloat16(w0 - __bfloat162float(h0));
            __nv_bfloat16 l1 = __float2bfloat16(w1 - __bfloat162float(h1));
            size_t o = (size_t)(n0 + nn) * H_DIM + k0 + 2 * pp;
            *(__nv_bfloat162*)&g_Whi[o] = __nv_bfloat162(h0, h1);
            *(__nv_bfloat162*)&g_Wlo[o] = __nv_bfloat162(l0, l1);
        }
    } else if (bx < 3072) {                // ---- conv h0 ----
        int idx = (bx - 2048) * 256 + tid;
        int h = idx & (H_DIM - 1);
        int b = idx >> 10;
        float v = hidden0[idx];
        __nv_bfloat16 hi = __float2bfloat16(v);
        __nv_bfloat16 lo = __float2bfloat16(v - __bfloat162float(hi));
        g_A[0][(size_t)b * 2048 + h]        = hi;
        g_A[0][(size_t)b * 2048 + 1024 + h] = lo;
    } else {                               // ---- zero rdy ----
        g_rdy[(bx - 3072) * 256 + tid] = 0u;
    }
}

// pre v3: block = fixed b, 64 timesteps; weights live in registers per thread.
__global__ void __launch_bounds__(256)
pre_kernel(const float* __restrict__ inputs,
           const float* __restrict__ actions,
           const float* __restrict__ i2h,
           const float* __restrict__ a2h,
           const void*  __restrict__ kact_ptr,
           float* __restrict__ out) {
    __shared__ float sinA[64 * I_DIM];
    __shared__ float sactA[64 * A_DIM];
    __shared__ float sk;
    const int b  = blockIdx.x & (B_DIM - 1);
    const int t0 = (blockIdx.x >> 8) << 6;
    const int tid = threadIdx.x;

    for (int e = tid; e < 64 * I_DIM; e += 256) {
        int j = e / I_DIM, i = e - j * I_DIM;
        sinA[e] = inputs[((size_t)(t0 + j) * B_DIM + b) * I_DIM + i];
    }
    for (int e = tid; e < 64 * A_DIM; e += 256) {
        int j = e >> 2, a = e & 3;
        sactA[e] = actions[((size_t)(t0 + j) * B_DIM + b) * A_DIM + a];
    }
    if (tid == 0) sk = decode_k(kact_ptr);
    __syncthreads();

    const int h = tid * 4;
    float4 rb = *(const float4*)&g_rbias[b * H_DIM + h];
    float4 wi[I_DIM], wa[A_DIM];
#pragma unroll
    for (int i = 0; i < I_DIM; ++i) wi[i] = *(const float4*)&i2h[i * H_DIM + h];
#pragma unroll
    for (int a = 0; a < A_DIM; ++a) wa[a] = *(const float4*)&a2h[a * H_DIM + h];
    const float k = sk;

    for (int j = 0; j < 64; ++j) {
        float4 s = rb;
#pragma unroll
        for (int i = 0; i < I_DIM; ++i) {
            float x = sinA[j * I_DIM + i];
            s.x = fmaf(x, wi[i].x, s.x); s.y = fmaf(x, wi[i].y, s.y);
            s.z = fmaf(x, wi[i].z, s.z); s.w = fmaf(x, wi[i].w, s.w);
        }
#pragma unroll
        for (int a = 0; a < A_DIM; ++a) {
            float x = k * sactA[j * A_DIM + a];
            s.x = fmaf(x, wa[a].x, s.x); s.y = fmaf(x, wa[a].y, s.y);
            s.z = fmaf(x, wa[a].z, s.z); s.w = fmaf(x, wa[a].w, s.w);
        }
        *(float4*)&out[((size_t)(t0 + j) * B_DIM + b) * H_DIM + h] = s;
    }
}

// ---------------------------------------------------------------------------
// Persistent recurrence kernel (R16 base + 6 acc chains + rotated prefetch)
// ---------------------------------------------------------------------------
__device__ __forceinline__ float tanh_fast(float x) {
    float e = __expf(2.0f * x);
    return 1.0f - __fdividef(2.0f, e + 1.0f);
}
__device__ __forceinline__ uint32_t smem_u32(const void* p) {
    uint32_t a;
    asm("{ .reg .u64 t; cvta.to.shared.u64 t, %1; cvt.u32.u64 %0, t; }" : "=r"(a) : "l"(p));
    return a;
}
__device__ __forceinline__ unsigned ld_acq(const unsigned* p) {
    unsigned v;
    asm volatile("ld.acquire.gpu.global.u32 %0, [%1];" : "=r"(v) : "l"(p) : "memory");
    return v;
}
#define CP_ASYNC16(dst, src) \
    asm volatile("cp.async.cg.shared.global [%0], [%1], 16;" :: "r"(dst), "l"(src))
#define CP_COMMIT() asm volatile("cp.async.commit_group;" ::: "memory")
#define CP_WAIT(n)  asm volatile("cp.async.wait_group %0;" :: "n"(n) : "memory")

__device__ __forceinline__ void mma16816(float* c, const uint32_t* a, const uint32_t* b) {
    asm volatile(
        "mma.sync.aligned.m16n8k16.row.col.f32.bf16.bf16.f32 "
        "{%0,%1,%2,%3}, {%4,%5,%6,%7}, {%8,%9}, {%0,%1,%2,%3};"
        : "+f"(c[0]), "+f"(c[1]), "+f"(c[2]), "+f"(c[3])
        : "r"(a[0]), "r"(a[1]), "r"(a[2]), "r"(a[3]), "r"(b[0]), "r"(b[1]));
}
__device__ __forceinline__ void ldsm4(uint32_t* r, uint32_t addr) {
    asm volatile("ldmatrix.sync.aligned.m8n8.x4.shared.b16 {%0,%1,%2,%3}, [%4];"
        : "=r"(r[0]), "=r"(r[1]), "=r"(r[2]), "=r"(r[3]) : "r"(addr));
}

// smem words: Whi[32][516] @0, Wlo @16512, A ring: 4 bufs of 64x68 @33024
#define WS_STRIDE 516
#define WLO_OFF   16512
#define ABUF_OFF  33024
#define ABUF_SZ   4352
#define A_STRIDE  68
#define SMEM_P_WORDS (ABUF_OFF + 4 * ABUF_SZ)        // 50432
#define SMEM_P_BYTES (SMEM_P_WORDS * 4)              // 201728
#define NSEQ 16

__global__ void __launch_bounds__(256, 1)
rnn_persistent(const float* __restrict__ hidden0,
               const float* __restrict__ rr,
               float* __restrict__ out) {
    extern __shared__ uint32_t smw[];
    const int tid  = threadIdx.x;
    const int wid  = tid >> 5;
    const int lane = tid & 31;
    const int gid  = lane >> 2;
    const int tig  = lane & 3;
    const int wm   = wid >> 1;           // 0..3 (16-row slabs)
    const int wn   = wid & 1;            // 0..1 (16-col slabs)
    const int n_grp = blockIdx.x & 31;
    const int m_grp = blockIdx.x >> 5;
    const int m0 = m_grp * 64;
    const int n0 = n_grp * 32;

    // ---- W slice (hi+lo) into smem once ----
    for (int e = tid; e < 32 * 128; e += 256) {
        int n = e >> 7, c = e & 127;
        uint4 vh = *(const uint4*)&g_Whi[(size_t)(n0 + n) * H_DIM + c * 8];
        uint4 vl = *(const uint4*)&g_Wlo[(size_t)(n0 + n) * H_DIM + c * 8];
        *(uint4*)&smw[n * WS_STRIDE + c * 4]           = vh;
        *(uint4*)&smw[WLO_OFF + n * WS_STRIDE + c * 4] = vl;
    }

    // ---- prev hidden tile + inertia in registers ----
    float hprev[2][4];
    float2 rv[2];
#pragma unroll
    for (int nt = 0; nt < 2; ++nt) {
        int c = n0 + wn * 16 + nt * 8 + tig * 2;
        rv[nt] = *(const float2*)&rr[c];
#pragma unroll
        for (int half = 0; half < 2; ++half) {
            int row = m0 + wm * 16 + gid + half * 8;
            float2 hp = *(const float2*)&hidden0[(size_t)row * H_DIM + c];
            hprev[nt][half * 2]     = hp.x;
            hprev[nt][half * 2 + 1] = hp.y;
        }
    }

    // ldmatrix lane word-offsets (fixed)
    const uint32_t sbase = smem_u32(smw);
    const int a_lane_off = (wm * 16 + (lane & 15)) * A_STRIDE + ((lane >> 4) << 2);
    const int b_lane_row = wn * 16 + (lane & 7) + ((lane >> 4) << 3);
    const int b_lane_off = b_lane_row * WS_STRIDE + (((lane >> 3) & 1) << 2);

    __syncthreads();

    // issue chunk (sequence j) from a given A parity base.
    // j even -> A-hi col-group j/2; j odd -> A-lo col-group j/2. Buffer = j & 3.
    auto issue = [&](const __nv_bfloat16* Abase, int j) {
        const int grp = j >> 1;
        const __nv_bfloat16* Ab = Abase + (size_t)m0 * 2048
                                        + ((j & 1) ? 1024 : 0) + (grp << 7);
        const uint32_t base = sbase + (uint32_t)(ABUF_OFF + (j & 3) * ABUF_SZ) * 4;
#pragma unroll
        for (int q = 0; q < 4; ++q) {
            int idx = tid + (q << 8);
            int row = idx >> 4, seg = idx & 15;
            CP_ASYNC16(base + (uint32_t)(row * A_STRIDE + seg * 4) * 4,
                       (const void*)(Ab + (size_t)row * 2048 + seg * 8));
        }
        CP_COMMIT();
    };
    // dataflow wait: 128-col group g of step ts gated by its 4 producers
    auto wait_g = [&](int ts, int g) {
        if (ts == 0) return;
        const unsigned* p = &g_rdy[((ts << 2) + m_grp) * 8 + g];
        while (ld_acq(p) < 4u) __nanosleep(40);
    };

    // ---- prologue: first 4 chunks of step 0 (no gating: prep done) ----
    issue(g_A[0], 0); issue(g_A[0], 1);
    issue(g_A[0], 2); issue(g_A[0], 3);

    for (int t = 0; t < T_DIM; ++t) {
        const __nv_bfloat16* __restrict__ A     = g_A[t & 1];
        __nv_bfloat16* __restrict__       Anext = g_A[(t + 1) & 1];
        float* __restrict__ outt = out + (size_t)t * (B_DIM * H_DIM);

        // 6 independent accumulator chains (3 terms x 2 n-tiles)
        float accA[2][4], accB[2][4], accC[2][4];
#pragma unroll
        for (int nt = 0; nt < 2; ++nt)
#pragma unroll
            for (int q = 0; q < 4; ++q) {
                accA[nt][q] = 0.f; accB[nt][q] = 0.f; accC[nt][q] = 0.f;
            }

        // Prefetch pre tile into registers (hidden under the GEMM)
        float2 pre_r[2][2];
#pragma unroll
        for (int nt = 0; nt < 2; ++nt) {
            const int c = n0 + wn * 16 + nt * 8 + tig * 2;
#pragma unroll
            for (int half = 0; half < 2; ++half) {
                const int row = m0 + wm * 16 + gid + half * 8;
                pre_r[nt][half] = *(const float2*)(outt + (size_t)row * H_DIM + c);
            }
        }

        // paired MMA: hi buf (seq 2p) + lo buf (seq 2p+1), shared bh fragments
        auto mma_pair = [&](int p) {
            const int abuf_h = ABUF_OFF + ((2 * p) & 3) * ABUF_SZ;
            const int abuf_l = ABUF_OFF + ((2 * p + 1) & 3) * ABUF_SZ;
            const int kw = p << 6;               // col-group word offset in W rows
#pragma unroll
            for (int k16 = 0; k16 < 8; ++k16) {
                const int ao = k16 * 8;
                const int kb = kw + k16 * 8;
                uint32_t af_h[4], af_l[4], bh_[4], bl_[4];
                ldsm4(af_h, sbase + (uint32_t)(abuf_h + a_lane_off + ao) * 4);
                ldsm4(bh_,  sbase + (uint32_t)(b_lane_off + kb) * 4);
                ldsm4(af_l, sbase + (uint32_t)(abuf_l + a_lane_off + ao) * 4);
                ldsm4(bl_,  sbase + (uint32_t)(WLO_OFF + b_lane_off + kb) * 4);
                // 6 mutually-independent MMAs (one per chain)
                mma16816(accA[0], af_h, bh_);
                mma16816(accA[1], af_h, bh_ + 2);
                mma16816(accB[0], af_h, bl_);
                mma16816(accB[1], af_h, bl_ + 2);
                mma16816(accC[0], af_l, bh_);
                mma16816(accC[1], af_l, bh_ + 2);
            }
        };

        for (int p = 0; p < NSEQ / 2; ++p) {
            if (p < NSEQ / 2 - 1) { CP_WAIT(2); } else { CP_WAIT(0); }
            __syncthreads();
            mma_pair(p);
            if (2 * p + 4 < NSEQ) {
                wait_g(t, p + 2);
                issue(A, 2 * p + 4);
                issue(A, 2 * p + 5);
            }
        }

        // ---- epilogue: combine chains, tanh + blend; publish Anext ----
#pragma unroll
        for (int nt = 0; nt < 2; ++nt) {
            const int c = n0 + wn * 16 + nt * 8 + tig * 2;
#pragma unroll
            for (int half = 0; half < 2; ++half) {
                const int row = m0 + wm * 16 + gid + half * 8;
                const float ax = (accA[nt][half * 2]     + accB[nt][half * 2])
                               + accC[nt][half * 2];
                const float ay = (accA[nt][half * 2 + 1] + accB[nt][half * 2 + 1])
                               + accC[nt][half * 2 + 1];
                float tt, h0, h1;
                tt = tanh_fast(pre_r[nt][half].x + ax);
                h0 = tt + rv[nt].x * (hprev[nt][half * 2] - tt);
                tt = tanh_fast(pre_r[nt][half].y + ay);
                h1 = tt + rv[nt].y * (hprev[nt][half * 2 + 1] - tt);
                hprev[nt][half * 2]     = h0;
                hprev[nt][half * 2 + 1] = h1;

                if (t < T_DIM - 1) {
                    __nv_bfloat16 a0 = __float2bfloat16(h0);
                    __nv_bfloat16 a1 = __float2bfloat16(h1);
                    __nv_bfloat16* hip = Anext + (size_t)row * 2048 + c;
                    *(__nv_bfloat162*)hip = __nv_bfloat162(a0, a1);
                    __nv_bfloat16 l0 = __float2bfloat16(h0 - __bfloat162float(a0));
                    __nv_bfloat16 l1 = __float2bfloat16(h1 - __bfloat162float(a1));
                    *(__nv_bfloat162*)(hip + 1024) = __nv_bfloat162(l0, l1);
                }
            }
        }

        if (t < T_DIM - 1) {
            __threadfence();
            __syncthreads();
            if (tid == 0) {
                asm volatile("red.release.gpu.global.add.u32 [%0], 1;"
                    :: "l"(&g_rdy[(((t + 1) << 2) + m_grp) * 8 + (n_grp >> 2)])
                    : "memory");
            }
            // rotated prefetch: first 4 chunks of step t+1 (LDG latency hides
            // under the deferred out stores below)
            wait_g(t + 1, 0);
            issue(Anext, 0); issue(Anext, 1);
            wait_g(t + 1, 1);
            issue(Anext, 2); issue(Anext, 3);
        }

        // deferred fp32 out store (off the inter-CTA critical path)
#pragma unroll
        for (int nt = 0; nt < 2; ++nt) {
            const int c = n0 + wn * 16 + nt * 8 + tig * 2;
#pragma unroll
            for (int half = 0; half < 2; ++half) {
                const int row = m0 + wm * 16 + gid + half * 8;
                *(float2*)(outt + (size_t)row * H_DIM + c) =
                    make_float2(hprev[nt][half * 2], hprev[nt][half * 2 + 1]);
            }
        }
    }
}

// ---------------------------------------------------------------------------
// Launch: prep -> pre -> persistent (3 launches, graph-capturable)
// ---------------------------------------------------------------------------
extern "C" void kernel_launch(void* const* d_in, const int* in_sizes, int n_in,
                              void* d_out, int out_size) {
    const float* inputs  = (const float*)d_in[0];
    const float* hidden0 = (const float*)d_in[1];
    const float* actions = (const float*)d_in[2];
    const float* reward  = (const float*)d_in[3];
    const float* i2h     = (const float*)d_in[4];
    const float* h2h     = (const float*)d_in[5];
    const float* a2h     = (const float*)d_in[6];
    const float* r2h     = (const float*)d_in[7];
    const float* bh      = (const float*)d_in[8];
    const float* r       = (const float*)d_in[9];
    const void*  kact    = d_in[10];
    float* out = (float*)d_out;

    static int attr_done = 0;
    if (!attr_done) {
        cudaFuncSetAttribute(rnn_persistent,
                             cudaFuncAttributeMaxDynamicSharedMemorySize, SMEM_P_BYTES);
        attr_done = 1;
    }

    prep_kernel<<<3104, 256>>>(reward, r2h, bh, h2h, hidden0);
    pre_kernel<<<(T_DIM / 64) * B_DIM, 256>>>(inputs, actions, i2h, a2h, kact, out);
    rnn_persistent<<<GRID_P, 256, SMEM_P_BYTES>>>(hidden0, r, out);
}